// round 17
// baseline (speedup 1.0000x reference)
#include <cuda_runtime.h>
#include <cuda_fp16.h>
#include <cstdint>

#define B_ 2
#define T_ 2048
#define C_ 1024
#define H_ 16
#define D_ 64

// ---- scratch (no cudaMalloc allowed) ----
__device__ __half g_q[(size_t)B_ * H_ * T_ * 2 * D_];      // [z][t][hi(64)|lo(64)] fp16
__device__ __half g_k[(size_t)B_ * H_ * T_ * 2 * D_];
__device__ __half g_v[(size_t)B_ * H_ * D_ * T_];          // [b][h][d][t] fp16 (transposed)
__device__ float  g_s[(size_t)B_ * H_ * T_ * T_];          // scores fp32
__device__ __half g_p[(size_t)B_ * H_ * T_ * T_];          // probs fp16
__device__ float  g_o[(size_t)B_ * T_ * C_];               // [b][t][h*64+d]

__device__ __forceinline__ uint32_t smem_u32(const void* p) {
    uint32_t a;
    asm("{ .reg .u64 t; cvta.to.shared.u64 t, %1; cvt.u32.u64 %0, t; }" : "=r"(a) : "l"(p));
    return a;
}

// m16n8k16 fp16 mma, fp32 accumulate (baseline PTX, sm_70+)
#define MMA_F16(c, a, b)                                                         \
    asm volatile("mma.sync.aligned.m16n8k16.row.col.f32.f16.f16.f32 "            \
                 "{%0,%1,%2,%3}, {%4,%5,%6,%7}, {%8,%9}, {%0,%1,%2,%3};"         \
                 : "+f"((c)[0]), "+f"((c)[1]), "+f"((c)[2]), "+f"((c)[3])        \
                 : "r"((a)[0]), "r"((a)[1]), "r"((a)[2]), "r"((a)[3]),           \
                   "r"((b)[0]), "r"((b)[1]))

#define LDSM_X4(r, a)                                                            \
    asm volatile("ldmatrix.sync.aligned.m8n8.x4.shared.b16 {%0,%1,%2,%3}, [%4];" \
                 : "=r"((r)[0]), "=r"((r)[1]), "=r"((r)[2]), "=r"((r)[3])        \
                 : "r"(a))
#define LDSM_X2(r, a)                                                            \
    asm volatile("ldmatrix.sync.aligned.m8n8.x2.shared.b16 {%0,%1}, [%2];"       \
                 : "=r"((r)[0]), "=r"((r)[1])                                    \
                 : "r"(a))

// ============================================================================
// fp16 projection GEMM (R15-proven):  C[m,n] = sum_k A[m,k] * B[n,k]  (NT)
// ============================================================================
template <int MODE, bool SPLIT>
__global__ __launch_bounds__(256, 2) void proj_f16(
    const float* __restrict__ A, const float* __restrict__ Bm,
    float* __restrict__ Cout, const float* __restrict__ bias,
    __half* __restrict__ CoutH, int K, int lda, int ldb)
{
    constexpr int HKP = 40;
    constexpr int ROWB = HKP * 2;
    constexpr int TSZ = 128 * HKP;
    __shared__ __half smh[(SPLIT ? 4 : 2) * TSZ];
    __half* Ah = smh;
    __half* Al = Ah + (SPLIT ? TSZ : 0);
    __half* Bh = Ah + (SPLIT ? 2 : 1) * TSZ;
    __half* Bl = Bh + (SPLIT ? TSZ : 0);

    const int tid = threadIdx.x;
    const int w = tid >> 5, lane = tid & 31;
    const int gid = lane >> 2, tig = lane & 3;
    const int wm = w & 1, wn = w >> 1;
    const int warp_m0 = wm * 64;
    const int warp_n0 = wn * 32;

    const int m0 = blockIdx.y * 128;
    const int n0 = blockIdx.x * 128;

    const int sr = tid >> 1;
    const int sc = (tid & 1) * 16;

    const uint32_t aB = smem_u32(Ah) + (uint32_t)((warp_m0 + (lane & 15)) * ROWB + (lane >> 4) * 16);
    const uint32_t bB = smem_u32(Bh) + (uint32_t)((warp_n0 + (lane & 7)) * ROWB + ((lane >> 3) & 1) * 16);
    constexpr uint32_t LOFF = (uint32_t)TSZ * 2;

    float acc[4][4][4];
#pragma unroll
    for (int i = 0; i < 4; i++)
#pragma unroll
        for (int j = 0; j < 4; j++)
#pragma unroll
            for (int t = 0; t < 4; t++) acc[i][j][t] = 0.0f;

    float4 pa[4], pb[4];
    auto loadA = [&](int k0) {
#pragma unroll
        for (int i = 0; i < 4; i++)
            pa[i] = *(const float4*)(A + (long long)(m0 + sr) * lda + k0 + sc + i * 4);
    };
    auto loadB = [&](int k0) {
#pragma unroll
        for (int i = 0; i < 4; i++)
            pb[i] = *(const float4*)(Bm + (long long)(n0 + sr) * ldb + k0 + sc + i * 4);
    };
    auto stageMat = [&](const float4* p, __half* Mh, __half* Ml) {
        uint32_t hu[8], lu[8];
#pragma unroll
        for (int i = 0; i < 4; i++) {
            __half2 h0 = __floats2half2_rn(p[i].x, p[i].y);
            __half2 h1 = __floats2half2_rn(p[i].z, p[i].w);
            hu[i * 2]     = *(uint32_t*)&h0;
            hu[i * 2 + 1] = *(uint32_t*)&h1;
            if (SPLIT) {
                __half2 l0 = __floats2half2_rn(p[i].x - __low2float(h0), p[i].y - __high2float(h0));
                __half2 l1 = __floats2half2_rn(p[i].z - __low2float(h1), p[i].w - __high2float(h1));
                lu[i * 2]     = *(uint32_t*)&l0;
                lu[i * 2 + 1] = *(uint32_t*)&l1;
            }
        }
        uint4* d = (uint4*)&Mh[sr * HKP + sc];
        d[0] = make_uint4(hu[0], hu[1], hu[2], hu[3]);
        d[1] = make_uint4(hu[4], hu[5], hu[6], hu[7]);
        if (SPLIT) {
            uint4* dl = (uint4*)&Ml[sr * HKP + sc];
            dl[0] = make_uint4(lu[0], lu[1], lu[2], lu[3]);
            dl[1] = make_uint4(lu[4], lu[5], lu[6], lu[7]);
        }
    };

    const int NC = K / 32;
    loadA(0); loadB(0);
    for (int c = 0; c < NC; c++) {
        __syncthreads();
        stageMat(pa, Ah, Al);
        stageMat(pb, Bh, Bl);
        __syncthreads();
        if (c + 1 < NC) { loadA((c + 1) * 32); loadB((c + 1) * 32); }

#pragma unroll
        for (int ks = 0; ks < 2; ks++) {
            uint32_t bh[4][2], bl[4][2];
#pragma unroll
            for (int nt = 0; nt < 4; nt++) {
                const uint32_t off = (uint32_t)(nt * 8 * ROWB + ks * 32);
                LDSM_X2(bh[nt], bB + off);
                if (SPLIT) LDSM_X2(bl[nt], bB + LOFF + off);
            }
#pragma unroll
            for (int mt = 0; mt < 4; mt++) {
                const uint32_t off = (uint32_t)(mt * 16 * ROWB + ks * 32);
                uint32_t ah[4], al[4];
                LDSM_X4(ah, aB + off);
                if (SPLIT) LDSM_X4(al, aB + LOFF + off);
#pragma unroll
                for (int nt = 0; nt < 4; nt++) {
                    MMA_F16(acc[mt][nt], ah, bh[nt]);
                    if (SPLIT) {
                        MMA_F16(acc[mt][nt], ah, bl[nt]);
                        MMA_F16(acc[mt][nt], al, bh[nt]);
                    }
                }
            }
        }
    }

    // ---------------- epilogue ----------------
#pragma unroll
    for (int mt = 0; mt < 4; mt++) {
#pragma unroll
        for (int nt = 0; nt < 4; nt++) {
            const int m = m0 + warp_m0 + mt * 16 + gid;
            const int n = n0 + warp_n0 + nt * 8 + tig * 2;
            const float* cc = acc[mt][nt];
#pragma unroll
            for (int r = 0; r < 2; r++) {
                const int mm = m + r * 8;
                const float v0 = cc[r * 2], v1 = cc[r * 2 + 1];
                if (MODE == 0) {
                    const int bb = mm >> 11, t = mm & (T_ - 1);
                    const int h = n >> 6, d0 = n & 63;
                    const long long base =
                        ((long long)(bb * H_ + h) * T_ + t) * (2 * D_) + d0;
                    __half h0 = __float2half_rn(v0);
                    __half h1 = __float2half_rn(v1);
                    __half l0 = __float2half_rn(v0 - __half2float(h0));
                    __half l1 = __float2half_rn(v1 - __half2float(h1));
                    *(__half2*)&CoutH[base]      = __halves2half2(h0, h1);
                    *(__half2*)&CoutH[base + D_] = __halves2half2(l0, l1);
                } else if (MODE == 4) {
                    const int bb = mm >> 11, t = mm & (T_ - 1);
#pragma unroll
                    for (int jj = 0; jj < 2; jj++) {
                        const int nn = n + jj;
                        const int h = nn >> 6, d0 = nn & 63;
                        CoutH[(((long long)(bb * H_ + h) * D_ + d0) * T_) + t] =
                            __float2half(jj ? v1 : v0);
                    }
                } else {
                    float2 f;
                    f.x = v0 + bias[n];
                    f.y = v1 + bias[n + 1];
                    *(float2*)&Cout[(long long)mm * C_ + n] = f;
                }
            }
        }
    }
}

// ============================================================================
// S kernel: S[z,m,n] = 8 * q.k  (fp16 3-term split, K=64, one-shot smem).
// Smem-staged coalesced epilogue (reuses Q/K smem as fp32 tile, RS=132).
// ============================================================================
__global__ __launch_bounds__(256, 2) void s_f16(
    const __half* __restrict__ Q, const __half* __restrict__ Kx,
    float* __restrict__ S)
{
    constexpr int SKP = 136;                 // halves per smem row (128 + 8)
    constexpr int ROWB = SKP * 2;            // 272 bytes
    constexpr int RS = 132;                  // fp32 out-tile row stride (div by 4)
    extern __shared__ __half sh[];
    __half* Aq = sh;
    __half* Bk = sh + 128 * SKP;
    float* ob = (float*)sh;                  // reused after compute

    const int tid = threadIdx.x;
    const int w = tid >> 5, lane = tid & 31;
    const int gid = lane >> 2, tig = lane & 3;
    const int wm = w & 1, wn = w >> 1;
    const int warp_m0 = wm * 64;
    const int warp_n0 = wn * 32;

    const int z = blockIdx.z;
    const int m0 = blockIdx.y * 128;
    const int n0 = blockIdx.x * 128;
    const __half* Qb = Q + (long long)z * T_ * (2 * D_) + (long long)m0 * (2 * D_);
    const __half* Kb = Kx + (long long)z * T_ * (2 * D_) + (long long)n0 * (2 * D_);

    const int sr = tid >> 1;
    const int ss = (tid & 1) * 64;
    {
        const uint4* qa = (const uint4*)(Qb + (long long)sr * (2 * D_) + ss);
        uint4* da = (uint4*)&Aq[sr * SKP + ss];
#pragma unroll
        for (int i = 0; i < 8; i++) da[i] = qa[i];
        const uint4* kb = (const uint4*)(Kb + (long long)sr * (2 * D_) + ss);
        uint4* db = (uint4*)&Bk[sr * SKP + ss];
#pragma unroll
        for (int i = 0; i < 8; i++) db[i] = kb[i];
    }
    __syncthreads();

    const uint32_t aB = smem_u32(Aq) + (uint32_t)((warp_m0 + (lane & 15)) * ROWB + (lane >> 4) * 16);
    const uint32_t bB = smem_u32(Bk) + (uint32_t)((warp_n0 + (lane & 7)) * ROWB + ((lane >> 3) & 1) * 16);
    constexpr uint32_t LOFF = 128;

    float acc[4][4][4];
#pragma unroll
    for (int i = 0; i < 4; i++)
#pragma unroll
        for (int j = 0; j < 4; j++)
#pragma unroll
            for (int t = 0; t < 4; t++) acc[i][j][t] = 0.0f;

#pragma unroll
    for (int ks = 0; ks < 4; ks++) {
        uint32_t bh[4][2], bl[4][2];
#pragma unroll
        for (int nt = 0; nt < 4; nt++) {
            const uint32_t off = (uint32_t)(nt * 8 * ROWB + ks * 32);
            LDSM_X2(bh[nt], bB + off);
            LDSM_X2(bl[nt], bB + LOFF + off);
        }
#pragma unroll
        for (int mt = 0; mt < 4; mt++) {
            const uint32_t off = (uint32_t)(mt * 16 * ROWB + ks * 32);
            uint32_t ah[4], al[4];
            LDSM_X4(ah, aB + off);
            LDSM_X4(al, aB + LOFF + off);
#pragma unroll
            for (int nt = 0; nt < 4; nt++) {
                MMA_F16(acc[mt][nt], ah, bh[nt]);
                MMA_F16(acc[mt][nt], ah, bl[nt]);
                MMA_F16(acc[mt][nt], al, bh[nt]);
            }
        }
    }

    // ---- epilogue: stage tile in smem, then coalesced 128B stores ----
    __syncthreads();                          // all LDSM done; smem reusable
#pragma unroll
    for (int mt = 0; mt < 4; mt++)
#pragma unroll
        for (int nt = 0; nt < 4; nt++) {
            const int row = warp_m0 + mt * 16 + gid;
            const int col = warp_n0 + nt * 8 + tig * 2;
            const float* cc = acc[mt][nt];
#pragma unroll
            for (int r = 0; r < 2; r++) {
                float2 f; f.x = cc[r * 2] * 8.0f; f.y = cc[r * 2 + 1] * 8.0f;
                *(float2*)&ob[(row + r * 8) * RS + col] = f;
            }
        }
    __syncthreads();
    {
        float* Sb = S + (long long)z * T_ * T_ + (long long)m0 * T_ + n0;
#pragma unroll
        for (int rb = 0; rb < 4; rb++) {
            const int row = w * 4 + (lane >> 3) + rb * 32;
#pragma unroll
            for (int i = 0; i < 4; i++) {
                const int col = (lane & 7) * 4 + i * 32;
                float4 f = *(const float4*)&ob[row * RS + col];
                *(float4*)&Sb[(long long)row * T_ + col] = f;
            }
        }
    }
}

// ============================================================================
// PV fp16 GEMM: O = P @ V^T_stored, fp16 in, fp32 out.
// Smem-staged coalesced epilogue; RS=68 (divisible by 4 -> aligned LDS.128).
// ============================================================================
__global__ __launch_bounds__(256, 2) void pv_fp16(
    const __half* __restrict__ P, const __half* __restrict__ V,
    float* __restrict__ Cout)
{
    constexpr int PKP = 40;
    constexpr int RS = 68;                   // fp32 out-tile row stride (64+4)
    __shared__ alignas(16) char smraw[128 * RS * 4];   // 34816 B; stage + out tile
    __half* Pt = (__half*)smraw;                       // 128*40*2 = 10240
    __half* Vt = Pt + 128 * PKP;                       // 64*40*2  =  5120
    float* ob  = (float*)smraw;

    const int tid = threadIdx.x;
    const int w = tid >> 5, lane = tid & 31;
    const int gid = lane >> 2, tig = lane & 3;
    const int wm = w & 3, wn = w >> 2;
    const int warp_m0 = wm * 32, warp_n0 = wn * 32;
    const int z = blockIdx.z;
    const int m0 = blockIdx.y * 128;
    const __half* Pb = P + (long long)z * T_ * T_ + (long long)m0 * T_;
    const __half* Vb = V + (long long)z * D_ * T_;

    const int lr = tid >> 2;
    const int lc = (tid & 3) * 8;

    const uint32_t aBase = smem_u32(Pt) +
        (uint32_t)((warp_m0 + (lane & 15)) * PKP * 2 + (lane >> 4) * 16);
    const uint32_t bBase = smem_u32(Vt) +
        (uint32_t)((warp_n0 + (lane & 7)) * PKP * 2 + ((lane >> 3) & 1) * 16);

    float acc[2][4][4];
#pragma unroll
    for (int i = 0; i < 2; i++)
#pragma unroll
        for (int j = 0; j < 4; j++)
#pragma unroll
            for (int t = 0; t < 4; t++) acc[i][j][t] = 0.0f;

    uint4 pp0, pp1, pv;
    auto loadG = [&](int k0) {
        pp0 = *(const uint4*)(Pb + (long long)lr * T_ + k0 + lc);
        pp1 = *(const uint4*)(Pb + (long long)(lr + 64) * T_ + k0 + lc);
        pv  = *(const uint4*)(Vb + (long long)lr * T_ + k0 + lc);
    };
    auto stage = [&]() {
        *(uint4*)&Pt[lr * PKP + lc] = pp0;
        *(uint4*)&Pt[(lr + 64) * PKP + lc] = pp1;
        *(uint4*)&Vt[lr * PKP + lc] = pv;
    };

    loadG(0);
    const int NC = T_ / 32;
    for (int c = 0; c < NC; c++) {
        __syncthreads();
        stage();
        __syncthreads();
        if (c + 1 < NC) loadG((c + 1) * 32);
#pragma unroll
        for (int ks = 0; ks < 2; ks++) {
            uint32_t bh[4][2];
#pragma unroll
            for (int nt = 0; nt < 4; nt++)
                LDSM_X2(bh[nt], bBase + (uint32_t)(nt * 8 * PKP * 2 + ks * 32));
#pragma unroll
            for (int mt = 0; mt < 2; mt++) {
                uint32_t ah[4];
                LDSM_X4(ah, aBase + (uint32_t)(mt * 16 * PKP * 2 + ks * 32));
#pragma unroll
                for (int nt = 0; nt < 4; nt++)
                    MMA_F16(acc[mt][nt], ah, bh[nt]);
            }
        }
    }

    // ---- epilogue: stage 128x64 fp32 tile in smem, coalesced row stores ----
    __syncthreads();                         // done with Pt/Vt
#pragma unroll
    for (int mt = 0; mt < 2; mt++)
#pragma unroll
        for (int nt = 0; nt < 4; nt++) {
            const int row = warp_m0 + mt * 16 + gid;
            const int col = warp_n0 + nt * 8 + tig * 2;
            const float* cc = acc[mt][nt];
#pragma unroll
            for (int r = 0; r < 2; r++) {
                float2 f; f.x = cc[r * 2]; f.y = cc[r * 2 + 1];
                *(float2*)&ob[(row + r * 8) * RS + col] = f;
            }
        }
    __syncthreads();
    {
        const int bb = z >> 4, h = z & 15;
#pragma unroll
        for (int rb = 0; rb < 8; rb++) {
            const int row = w * 2 + (lane >> 4) + rb * 16;
            const int col = (lane & 15) * 4;
            float4 f = *(const float4*)&ob[row * RS + col];
            *(float4*)&Cout[((long long)(bb * T_ + m0 + row)) * C_ + h * D_ + col] = f;
        }
    }
}

// ---------------------------------------------------------------------------
// Head-axis softmax (quirk: softmax over dim=1 == H). fp32 S -> fp16 P.
// ---------------------------------------------------------------------------
__global__ __launch_bounds__(256) void softmax_head_kernel(const float* __restrict__ s,
                                                           __half* __restrict__ p)
{
    const long long idx = (long long)blockIdx.x * blockDim.x + threadIdx.x;
    const long long hs = (long long)T_ * T_;
    const int k4 = (int)(idx & (T_ / 4 - 1)) * 4;
    const long long bq = idx >> 9;
    const int b = (int)(bq >> 11);
    const int q = (int)(bq & (T_ - 1));
    const long long base = (((long long)b * H_) * T_ + q) * T_ + k4;

    float4 v[H_];
    float4 mx = make_float4(-1e30f, -1e30f, -1e30f, -1e30f);
#pragma unroll
    for (int h = 0; h < H_; h++) {
        v[h] = *(const float4*)&s[base + (long long)h * hs];
        mx.x = fmaxf(mx.x, v[h].x); mx.y = fmaxf(mx.y, v[h].y);
        mx.z = fmaxf(mx.z, v[h].z); mx.w = fmaxf(mx.w, v[h].w);
    }
    float4 sum = make_float4(0.f, 0.f, 0.f, 0.f);
#pragma unroll
    for (int h = 0; h < H_; h++) {
        v[h].x = __expf(v[h].x - mx.x); v[h].y = __expf(v[h].y - mx.y);
        v[h].z = __expf(v[h].z - mx.z); v[h].w = __expf(v[h].w - mx.w);
        sum.x += v[h].x; sum.y += v[h].y; sum.z += v[h].z; sum.w += v[h].w;
    }
    const float ix = 1.0f / sum.x, iy = 1.0f / sum.y;
    const float iz = 1.0f / sum.z, iw = 1.0f / sum.w;
#pragma unroll
    for (int h = 0; h < H_; h++) {
        __half2 h01 = __floats2half2_rn(v[h].x * ix, v[h].y * iy);
        __half2 h23 = __floats2half2_rn(v[h].z * iz, v[h].w * iw);
        uint2 pk;
        pk.x = *(uint32_t*)&h01;
        pk.y = *(uint32_t*)&h23;
        *(uint2*)&p[base + (long long)h * hs] = pk;
    }
}

// ---------------------------------------------------------------------------
extern "C" void kernel_launch(void* const* d_in, const int* in_sizes, int n_in,
                              void* d_out, int out_size)
{
    const float* query_src = (const float*)d_in[0];
    const float* key_src   = (const float*)d_in[1];
    const float* value_src = (const float*)d_in[2];
    const float* Wq        = (const float*)d_in[3];
    const float* Wk        = (const float*)d_in[4];
    const float* Wv        = (const float*)d_in[5];
    const float* Wo        = (const float*)d_in[6];
    const float* bo        = (const float*)d_in[7];
    float* out = (float*)d_out;

    __half *q, *k, *v, *p;
    float *s, *o;
    cudaGetSymbolAddress((void**)&q, g_q);
    cudaGetSymbolAddress((void**)&k, g_k);
    cudaGetSymbolAddress((void**)&v, g_v);
    cudaGetSymbolAddress((void**)&s, g_s);
    cudaGetSymbolAddress((void**)&p, g_p);
    cudaGetSymbolAddress((void**)&o, g_o);

    // dynamic smem for s_f16: max(QK tiles 69632 B, out tile 128*132*4 = 67584 B)
    const int SM_S = 2 * 128 * 136 * 2;
    cudaFuncSetAttribute(s_f16, cudaFuncAttributeMaxDynamicSharedMemorySize, SM_S);

    const dim3 blk(256);

    // Pass 1: projections.
    {
        dim3 grid(C_ / 128, (B_ * T_) / 128, 1);
        proj_f16<0, true><<<grid, blk>>>(query_src, Wq, nullptr, nullptr, q, C_, C_, C_);
        proj_f16<0, true><<<grid, blk>>>(key_src,   Wk, nullptr, nullptr, k, C_, C_, C_);
        proj_f16<4, false><<<grid, blk>>>(value_src, Wv, nullptr, nullptr, v, C_, C_, C_);
    }
    // Pass 2: S = 8 * q.k (fp16 3-term split, K=64)
    {
        dim3 grid(T_ / 128, T_ / 128, B_ * H_);
        s_f16<<<grid, blk, SM_S>>>(q, k, s);
    }
    // Pass 3: softmax over HEAD axis: fp32 S -> fp16 P
    {
        const long long total = (long long)B_ * T_ * (T_ / 4);
        softmax_head_kernel<<<(unsigned)(total / 256), 256>>>(s, p);
    }
    // Pass 4: O = P @ V (fp16 mma) -> fp32 [b][q][h*64+d]
    {
        dim3 grid(1, T_ / 128, B_ * H_);
        pv_fp16<<<grid, blk>>>(p, v, o);
    }
    // Pass 5: out = O @ Wo^T + bo (fp16 single)
    {
        dim3 grid(C_ / 128, (B_ * T_) / 128, 1);
        proj_f16<3, false><<<grid, blk>>>(o, Wo, out, bo, nullptr, C_, C_, C_);
    }
}